// round 16
// baseline (speedup 1.0000x reference)
#include <cuda_runtime.h>
#include <cuda_bf16.h>
#include <math.h>
#include <stdint.h>

// ---------------------------------------------------------------------------
// LINKX forward (R16 = R15 mainloop + R9 algebra fusion, properly isolated).
//   z5 = cat@ww1 + bw1 = hb@(wx2@W5t) + h2b@(wa2@W5b) + b5'
//   -> G5 launch eliminated; folded as second N-half into G2 and G4.
//   z5a (main) and z5b (side) kept separate so the two fused GEMMs are
//   independent; combine h = relu(relu(z5a+z5b)+hx+ha) folds into G6 staging.
//   main: compose -> b5' -> prep -> G1 -> [G2|G5a]  -> join -> G6
//   side: binning -> gather -> G3 -> [G4|G5b]
// GEMMs: mma.sync bf16 2-term split (hh+hl+lh), k32 double-buffered cp.async.
// ---------------------------------------------------------------------------

#define NMAX   100000
#define EMAX   1600000
#define HID    128
#define INDIM  256

// fp32 buffers
__device__ float g_hx[(size_t)NMAX * HID];
__device__ float g_ha[(size_t)NMAX * HID];
__device__ float g_z5a[(size_t)NMAX * HID];
__device__ float g_z5b[(size_t)NMAX * HID];
__device__ float g_uv[2 * 128 * 128];
__device__ float g_b5[128];
__device__ float g_zero[128];                       // never written: stays 0
// bf16-split activation planes (hi plane then lo plane)
__device__ __align__(16) __nv_bfloat16 g_xs[2 * (size_t)NMAX * INDIM];
__device__ __align__(16) __nv_bfloat16 g_hb[2 * (size_t)NMAX * HID];
__device__ __align__(16) __nv_bfloat16 g_h2b[2 * (size_t)NMAX * HID];
__device__ __align__(16) __nv_bfloat16 g_aggb[2 * (size_t)NMAX * HID];
__device__ __align__(16) __nv_bfloat16 g_wt[245760];
// binning scratch
__device__ int g_cnt[NMAX];
__device__ int g_cur[NMAX];
__device__ int g_off[NMAX + 1];
__device__ int g_bins[EMAX];

// ---- helpers --------------------------------------------------------------
__device__ __forceinline__ uint32_t smem_u32(const void* p) {
    uint32_t a;
    asm("{ .reg .u64 t; cvta.to.shared.u64 t, %1; cvt.u32.u64 %0, t; }"
        : "=r"(a) : "l"(p));
    return a;
}

#define LDSM_X4(r0, r1, r2, r3, addr) \
    asm volatile("ldmatrix.sync.aligned.m8n8.x4.shared.b16 {%0,%1,%2,%3}, [%4];" \
                 : "=r"(r0), "=r"(r1), "=r"(r2), "=r"(r3) : "r"(addr))

#define MMA_BF16(acc, a, b0v, b1v) \
    asm volatile("mma.sync.aligned.m16n8k16.row.col.f32.bf16.bf16.f32 " \
                 "{%0,%1,%2,%3}, {%4,%5,%6,%7}, {%8,%9}, {%0,%1,%2,%3};" \
                 : "+f"((acc)[0]), "+f"((acc)[1]), "+f"((acc)[2]), "+f"((acc)[3]) \
                 : "r"((a)[0]), "r"((a)[1]), "r"((a)[2]), "r"((a)[3]), \
                   "r"(b0v), "r"(b1v))

#define CP_ASYNC16(smem, gmem) \
    asm volatile("cp.async.cg.shared.global [%0], [%1], 16;" \
                 :: "r"(smem), "l"(gmem))
#define CP_COMMIT() asm volatile("cp.async.commit_group;")
#define CP_WAIT1()  asm volatile("cp.async.wait_group 1;")
#define CP_WAIT0()  asm volatile("cp.async.wait_group 0;")

__device__ __forceinline__ uint32_t pack_bf2(__nv_bfloat16 lo, __nv_bfloat16 hi) {
    __nv_bfloat162 p;
    p.x = lo; p.y = hi;
    return *reinterpret_cast<uint32_t*>(&p);
}

__device__ __forceinline__ void bsplit(float x, __nv_bfloat16& h, __nv_bfloat16& l) {
    h = __float2bfloat16(x);
    l = __float2bfloat16(x - __bfloat162float(h));
}

// ---------------------------------------------------------------------------
// Binning aggregation (proven)
// ---------------------------------------------------------------------------
__global__ void zero_cnt(int* cnt, int* cur, int M) {
    int i = blockIdx.x * blockDim.x + threadIdx.x;
    if (i < M) { cnt[i] = 0; cur[i] = 0; }
}

__global__ void count_kernel(const int* __restrict__ ei, int* __restrict__ cnt, int E) {
    int i = blockIdx.x * blockDim.x + threadIdx.x;
    int stride = gridDim.x * blockDim.x;
    for (int e = i; e < E; e += stride)
        atomicAdd(&cnt[__ldg(&ei[E + e])], 1);
}

__global__ void scan_kernel(const int* __restrict__ cnt, int* __restrict__ off, int M) {
    __shared__ int part[1024];
    const int t = threadIdx.x;
    const int chunk = (M + 1023) >> 10;
    const int beg = t * chunk;
    const int end = min(beg + chunk, M);
    int s = 0;
    for (int i = beg; i < end; ++i) s += cnt[i];
    part[t] = s;
    __syncthreads();
    for (int d = 1; d < 1024; d <<= 1) {
        int v = (t >= d) ? part[t - d] : 0;
        __syncthreads();
        part[t] += v;
        __syncthreads();
    }
    int run = (t == 0) ? 0 : part[t - 1];
    for (int i = beg; i < end; ++i) { off[i] = run; run += cnt[i]; }
    if (t == 1023) off[M] = run;
}

__global__ void fill_kernel(const int* __restrict__ ei,
                            const int* __restrict__ off,
                            int* __restrict__ cur,
                            int* __restrict__ bins, int E) {
    int i = blockIdx.x * blockDim.x + threadIdx.x;
    int stride = gridDim.x * blockDim.x;
    for (int e = i; e < E; e += stride) {
        int src = __ldg(&ei[e]);
        int dst = __ldg(&ei[E + e]);
        int slot = atomicAdd(&cur[dst], 1);
        bins[off[dst] + slot] = src;
    }
}

__global__ void gather_kernel(const int* __restrict__ off,
                              const int* __restrict__ bins,
                              const float* __restrict__ emb,
                              __nv_bfloat16* __restrict__ aggh,
                              __nv_bfloat16* __restrict__ aggl, int M) {
    int w    = (blockIdx.x * blockDim.x + threadIdx.x) >> 5;
    int lane = threadIdx.x & 31;
    if (w >= M) return;
    int beg = __ldg(&off[w]);
    int end = __ldg(&off[w + 1]);
    float4 acc = make_float4(0.f, 0.f, 0.f, 0.f);
    int e = beg;
    for (; e + 1 < end; e += 2) {
        int s0 = __ldg(&bins[e]);
        int s1 = __ldg(&bins[e + 1]);
        float4 v0 = __ldg((const float4*)(emb + (size_t)s0 * HID + lane * 4));
        float4 v1 = __ldg((const float4*)(emb + (size_t)s1 * HID + lane * 4));
        acc.x += v0.x + v1.x; acc.y += v0.y + v1.y;
        acc.z += v0.z + v1.z; acc.w += v0.w + v1.w;
    }
    if (e < end) {
        int s0 = __ldg(&bins[e]);
        float4 v0 = __ldg((const float4*)(emb + (size_t)s0 * HID + lane * 4));
        acc.x += v0.x; acc.y += v0.y; acc.z += v0.z; acc.w += v0.w;
    }
    float inv = 1.0f / (float)max(end - beg, 1);
    __nv_bfloat16 h0,h1,h2,h3, l0,l1,l2,l3;
    bsplit(acc.x * inv, h0, l0);
    bsplit(acc.y * inv, h1, l1);
    bsplit(acc.z * inv, h2, l2);
    bsplit(acc.w * inv, h3, l3);
    size_t o = (size_t)w * HID + lane * 4;
    *(uint2*)(aggh + o) = make_uint2(pack_bf2(h0, h1), pack_bf2(h2, h3));
    *(uint2*)(aggl + o) = make_uint2(pack_bf2(l0, l1), pack_bf2(l2, l3));
}

// ---------------------------------------------------------------------------
__global__ void prep_x(const float4* __restrict__ x4,
                       __nv_bfloat16* __restrict__ xh,
                       __nv_bfloat16* __restrict__ xl, int n4) {
    int t = blockIdx.x * blockDim.x + threadIdx.x;
    if (t >= n4) return;
    float4 v = __ldg(&x4[t]);
    __nv_bfloat16 h0,h1,h2,h3, l0,l1,l2,l3;
    bsplit(v.x, h0, l0); bsplit(v.y, h1, l1);
    bsplit(v.z, h2, l2); bsplit(v.w, h3, l3);
    ((uint2*)xh)[t] = make_uint2(pack_bf2(h0, h1), pack_bf2(h2, h3));
    ((uint2*)xl)[t] = make_uint2(pack_bf2(l0, l1), pack_bf2(l2, l3));
}

// Composite weights: U = wx2@W5t, V = wa2@W5b (halves of ww1[256,128]).
__global__ void compose_kernel(const float* __restrict__ wx2,
                               const float* __restrict__ wa2,
                               const float* __restrict__ ww1,
                               float* __restrict__ UV) {
    int mat = blockIdx.y;
    int i = blockIdx.x;
    int j = threadIdx.x;
    const float* A  = mat ? wa2 : wx2;
    const float* Wp = ww1 + (mat ? 128 * 128 : 0);
    float s = 0.f;
#pragma unroll 8
    for (int k = 0; k < 128; ++k)
        s = fmaf(__ldg(&A[i * 128 + k]), __ldg(&Wp[k * 128 + j]), s);
    UV[mat * 16384 + i * 128 + j] = s;
}

// b5'[j] = bw1[j] + bx2@W5t[:,j] + ba2@W5b[:,j]
__global__ void bias5_kernel(const float* __restrict__ bx2,
                             const float* __restrict__ ba2,
                             const float* __restrict__ bw1,
                             const float* __restrict__ ww1,
                             float* __restrict__ b5) {
    int j = threadIdx.x;
    float s = bw1[j];
    for (int k = 0; k < 128; ++k) {
        s = fmaf(bx2[k], ww1[k * 128 + j], s);
        s = fmaf(ba2[k], ww1[(128 + k) * 128 + j], s);
    }
    b5[j] = s;
}

// ---------------------------------------------------------------------------
// Weight prep: split+transpose into B^T planes.
// g_wt layout (elements):
//   W1  (wx1,      N=128,K=256): h@0       l@32768
//   WB2 ([wx2|U],  N=256,K=128): h@65536   l@98304
//   W3  (wa1,      N=128,K=128): h@131072  l@147456
//   WB4 ([wa2|V],  N=256,K=128): h@163840  l@196608
//   W6  (wc pad64, N=64, K=128): h@229376  l@237568
__global__ void prep_all3(const float* __restrict__ wx1,
                          const float* __restrict__ wx2,
                          const float* __restrict__ wa1,
                          const float* __restrict__ wa2,
                          const float* __restrict__ UV,
                          const float* __restrict__ wc,
                          __nv_bfloat16* __restrict__ WT) {
    int t = blockIdx.x * blockDim.x + threadIdx.x;
    float v;
    __nv_bfloat16 *dh, *dl;
    if (t < 32768) {                        // wx1 [256,128] -> [128][256]
        int k = t >> 7, n = t & 127;
        v = wx1[t];
        dh = WT + (size_t)n * 256 + k;
        dl = dh + 32768;
    } else if (t < 49152) {                 // wx2 -> WB2 rows 0..127
        int u = t - 32768;
        int k = u >> 7, n = u & 127;
        v = wx2[u];
        dh = WT + 65536 + (size_t)n * 128 + k;
        dl = dh + 32768;
    } else if (t < 65536) {                 // U -> WB2 rows 128..255
        int u = t - 49152;
        int k = u >> 7, n = u & 127;
        v = UV[u];
        dh = WT + 65536 + (size_t)(128 + n) * 128 + k;
        dl = dh + 32768;
    } else if (t < 81920) {                 // wa1 -> W3
        int u = t - 65536;
        int k = u >> 7, n = u & 127;
        v = wa1[u];
        dh = WT + 131072 + (size_t)n * 128 + k;
        dl = dh + 16384;
    } else if (t < 98304) {                 // wa2 -> WB4 rows 0..127
        int u = t - 81920;
        int k = u >> 7, n = u & 127;
        v = wa2[u];
        dh = WT + 163840 + (size_t)n * 128 + k;
        dl = dh + 32768;
    } else if (t < 114688) {                // V -> WB4 rows 128..255
        int u = t - 98304;
        int k = u >> 7, n = u & 127;
        v = UV[16384 + u];
        dh = WT + 163840 + (size_t)(128 + n) * 128 + k;
        dl = dh + 32768;
    } else if (t < 122880) {                // wc padded -> W6
        int u = t - 114688;
        int n = u >> 7, k = u & 127;
        v = (n < 40) ? wc[k * 40 + n] : 0.f;
        dh = WT + 229376 + (size_t)n * 128 + k;
        dl = dh + 8192;
    } else return;
    __nv_bfloat16 h, l;
    bsplit(v, h, l);
    *dh = h;
    *dl = l;
}

// ---------------------------------------------------------------------------
// k32 double-buffered mainloop (R15, proven). bOffRows shifts the B^T rows.
// smem per stage: AH(0) AL(10240) BH(20480) BL(30720) bytes, 80B row stride.
template <int K_DIM>
__device__ __forceinline__ void mainloop_k32(
    const __nv_bfloat16* __restrict__ Ah, const __nv_bfloat16* __restrict__ Al,
    const __nv_bfloat16* __restrict__ Bh, const __nv_bfloat16* __restrict__ Bl,
    int bOffRows, int M, int bm, uint32_t uS, float acc[2][8][4]) {
    const int tid  = threadIdx.x;
    const int wid  = tid >> 5;
    const int lane = tid & 31;
    const int wm   = wid >> 1;
    const int wn   = wid & 1;

    const __nv_bfloat16* gp[8];
    uint32_t so[8];
#pragma unroll
    for (int i = 0; i < 8; ++i) {
        int u   = tid + i * 256;
        int p   = u >> 9;
        int rem = u & 511;
        int row = rem >> 2;
        int q   = rem & 3;
        so[i] = (uint32_t)(p * 10240 + row * 80 + q * 16);
        if (p == 0)      gp[i] = Ah + (size_t)min(bm + row, M - 1) * K_DIM + q * 8;
        else if (p == 1) gp[i] = Al + (size_t)min(bm + row, M - 1) * K_DIM + q * 8;
        else if (p == 2) gp[i] = Bh + (size_t)(bOffRows + row) * K_DIM + q * 8;
        else             gp[i] = Bl + (size_t)(bOffRows + row) * K_DIM + q * 8;
    }

#define ISSUE_STAGE(c, s) do {                                    \
        uint32_t _b = uS + (s) * 40960;                           \
        int _k0 = (c) * 32;                                       \
        _Pragma("unroll")                                         \
        for (int _i = 0; _i < 8; ++_i)                            \
            CP_ASYNC16(_b + so[_i], gp[_i] + _k0);                \
        CP_COMMIT();                                              \
    } while (0)

    const int a_r0 = (lane & 7) + ((lane >> 3) & 1) * 8;
    const int a_ch = lane >> 4;
    const int b_n0 = (lane & 7) + ((lane >> 4) & 1) * 8;
    const int b_ch = (lane >> 3) & 1;

    const int NC = K_DIM / 32;
    ISSUE_STAGE(0, 0);

    for (int c = 0; c < NC; ++c) {
        const int s = c & 1;
        if (c + 1 < NC) { ISSUE_STAGE(c + 1, (c + 1) & 1); CP_WAIT1(); }
        else            { CP_WAIT0(); }
        __syncthreads();

        const uint32_t base = uS + s * 40960;
#pragma unroll
        for (int kk = 0; kk < 2; ++kk) {
            const uint32_t koff = kk * 32 + (uint32_t)(a_ch * 16);
            uint32_t ah[2][4], al[2][4];
#pragma unroll
            for (int mt = 0; mt < 2; ++mt) {
                int arow = wm * 32 + mt * 16 + a_r0;
                LDSM_X4(ah[mt][0], ah[mt][1], ah[mt][2], ah[mt][3],
                        base + arow * 80 + koff);
                LDSM_X4(al[mt][0], al[mt][1], al[mt][2], al[mt][3],
                        base + 10240 + arow * 80 + koff);
            }
            const uint32_t bkoff = kk * 32 + (uint32_t)(b_ch * 16);
#pragma unroll
            for (int np = 0; np < 4; ++np) {
                int bn = wn * 64 + np * 16 + b_n0;
                uint32_t bh[4], bl[4];
                LDSM_X4(bh[0], bh[1], bh[2], bh[3],
                        base + 20480 + bn * 80 + bkoff);
                LDSM_X4(bl[0], bl[1], bl[2], bl[3],
                        base + 30720 + bn * 80 + bkoff);
#pragma unroll
                for (int mt = 0; mt < 2; ++mt) {
#pragma unroll
                    for (int t = 0; t < 2; ++t) {
                        float* a4 = acc[mt][np * 2 + t];
                        MMA_BF16(a4, ah[mt], bh[2 * t], bh[2 * t + 1]);
                        MMA_BF16(a4, ah[mt], bl[2 * t], bl[2 * t + 1]);
                        MMA_BF16(a4, al[mt], bh[2 * t], bh[2 * t + 1]);
                    }
                }
            }
        }
        __syncthreads();
    }
#undef ISSUE_STAGE
}

// ---------------------------------------------------------------------------
// G1/G3: C = relu(A @ W + bias), bf16-split planes out.
template <int K_DIM>
__global__ __launch_bounds__(256, 2)
void mma_split(const __nv_bfloat16* __restrict__ Ah,
               const __nv_bfloat16* __restrict__ Al,
               const __nv_bfloat16* __restrict__ Bh,
               const __nv_bfloat16* __restrict__ Bl,
               const float* __restrict__ bias,
               __nv_bfloat16* __restrict__ Ch,
               __nv_bfloat16* __restrict__ Cl, int M) {
    extern __shared__ __align__(16) __nv_bfloat16 S[];
    const uint32_t uS = smem_u32(S);
    const int bm = blockIdx.x * 128;

    float acc[2][8][4];
#pragma unroll
    for (int i = 0; i < 2; ++i)
#pragma unroll
        for (int j = 0; j < 8; ++j)
#pragma unroll
            for (int q = 0; q < 4; ++q) acc[i][j][q] = 0.f;

    mainloop_k32<K_DIM>(Ah, Al, Bh, Bl, 0, M, bm, uS, acc);

    const int wid = threadIdx.x >> 5, lane = threadIdx.x & 31;
    const int wm = wid >> 1, wn = wid & 1;
    const int lr = lane >> 2, lc = (lane & 3) * 2;
#pragma unroll
    for (int mt = 0; mt < 2; ++mt) {
#pragma unroll
        for (int g = 0; g < 8; ++g) {
            int col = wn * 64 + g * 8 + lc;
            float2 bv = *(const float2*)&bias[col];
#pragma unroll
            for (int half = 0; half < 2; ++half) {
                int r = bm + wm * 32 + mt * 16 + lr + half * 8;
                if (r >= M) continue;
                float z0 = fmaxf(acc[mt][g][2 * half + 0] + bv.x, 0.f);
                float z1 = fmaxf(acc[mt][g][2 * half + 1] + bv.y, 0.f);
                __nv_bfloat16 h0, l0, h1, l1;
                bsplit(z0, h0, l0);
                bsplit(z1, h1, l1);
                size_t o = (size_t)r * HID + col;
                *(uint32_t*)(Ch + o) = pack_bf2(h0, h1);
                *(uint32_t*)(Cl + o) = pack_bf2(l0, l1);
            }
        }
    }
}

// Fused N=256 GEMM (grid.y=2): y selects B^T rows [y*128, y*128+128) and
// output: y0 -> out0 = acc + bias0; y1 -> out1 = acc + bias1 (fp32, ld 128).
__global__ __launch_bounds__(256, 2)
void mma_fused2(const __nv_bfloat16* __restrict__ Ah,
                const __nv_bfloat16* __restrict__ Al,
                const __nv_bfloat16* __restrict__ Bh,
                const __nv_bfloat16* __restrict__ Bl,
                const float* __restrict__ bias0,
                float* __restrict__ out0,
                const float* __restrict__ bias1,
                float* __restrict__ out1, int M) {
    extern __shared__ __align__(16) __nv_bfloat16 S[];
    const uint32_t uS = smem_u32(S);
    const int bm = blockIdx.x * 128;
    const int y  = blockIdx.y;

    float acc[2][8][4];
#pragma unroll
    for (int i = 0; i < 2; ++i)
#pragma unroll
        for (int j = 0; j < 8; ++j)
#pragma unroll
            for (int q = 0; q < 4; ++q) acc[i][j][q] = 0.f;

    mainloop_k32<HID>(Ah, Al, Bh, Bl, y * 128, M, bm, uS, acc);

    const float* bias = y ? bias1 : bias0;
    float* outp       = y ? out1 : out0;
    const int wid = threadIdx.x >> 5, lane = threadIdx.x & 31;
    const int wm = wid >> 1, wn = wid & 1;
    const int lr = lane >> 2, lc = (lane & 3) * 2;
#pragma unroll
    for (int mt = 0; mt < 2; ++mt) {
#pragma unroll
        for (int g = 0; g < 8; ++g) {
            int col = wn * 64 + g * 8 + lc;
            float2 bv = *(const float2*)&bias[col];
#pragma unroll
            for (int half = 0; half < 2; ++half) {
                int r = bm + wm * 32 + mt * 16 + lr + half * 8;
                if (r >= M) continue;
                float z0 = acc[mt][g][2 * half + 0] + bv.x;
                float z1 = acc[mt][g][2 * half + 1] + bv.y;
                *(float2*)&outp[(size_t)r * 128 + col] = make_float2(z0, z1);
            }
        }
    }
}

// ---------------------------------------------------------------------------
// G6: out[M,40] = h @ wc + bc with h = relu(relu(z5a+z5b)+hx+ha) computed in
// staging. K=128, N=64 (wc padded). Based on R11 mma_out (proven).
__global__ __launch_bounds__(256, 2)
void mma_out4(const float* __restrict__ z5a,
              const float* __restrict__ z5b,
              const float* __restrict__ hx,
              const float* __restrict__ ha,
              const __nv_bfloat16* __restrict__ Bh,
              const __nv_bfloat16* __restrict__ Bl,
              const float* __restrict__ bias,
              float* __restrict__ out, int M) {
    __shared__ __align__(16) __nv_bfloat16 AH[128 * 24];
    __shared__ __align__(16) __nv_bfloat16 AL[128 * 24];
    __shared__ __align__(16) __nv_bfloat16 BHs[64 * 24];
    __shared__ __align__(16) __nv_bfloat16 BLs[64 * 24];

    const int tid  = threadIdx.x;
    const int wid  = tid >> 5;
    const int lane = tid & 31;
    const int bm   = blockIdx.x * 128;

    const uint32_t uAH = smem_u32(AH);
    const uint32_t uAL = smem_u32(AL);
    const uint32_t uBH = smem_u32(BHs);
    const uint32_t uBL = smem_u32(BLs);

    float acc[8][4];
#pragma unroll
    for (int j = 0; j < 8; ++j)
#pragma unroll
        for (int q = 0; q < 4; ++q) acc[j][q] = 0.f;

    const int a_r0 = (lane & 7) + ((lane >> 3) & 1) * 8;
    const int a_ch = lane >> 4;
    const int b_n0 = (lane & 7) + ((lane >> 4) & 1) * 8;
    const int b_ch = (lane >> 3) & 1;
    const int srow = tid >> 1;
    const int sh   = tid & 1;

    for (int c = 0; c < 8; ++c) {
        const int k0 = c * 16;
        {
            int gr = bm + srow;
            float v[8];
            if (gr < M) {
                size_t o = (size_t)gr * 128 + k0 + sh * 8;
#pragma unroll
                for (int q = 0; q < 2; ++q) {
                    float4 za = *(const float4*)&z5a[o + q * 4];
                    float4 zb = *(const float4*)&z5b[o + q * 4];
                    float4 aa = *(const float4*)&hx[o + q * 4];
                    float4 bb = *(const float4*)&ha[o + q * 4];
                    v[q*4+0] = fmaxf(fmaxf(za.x + zb.x, 0.f) + aa.x + bb.x, 0.f);
                    v[q*4+1] = fmaxf(fmaxf(za.y + zb.y, 0.f) + aa.y + bb.y, 0.f);
                    v[q*4+2] = fmaxf(fmaxf(za.z + zb.z, 0.f) + aa.z + bb.z, 0.f);
                    v[q*4+3] = fmaxf(fmaxf(za.w + zb.w, 0.f) + aa.w + bb.w, 0.f);
                }
            } else {
#pragma unroll
                for (int q = 0; q < 8; ++q) v[q] = 0.f;
            }
            __nv_bfloat16 h[8], l[8];
#pragma unroll
            for (int q = 0; q < 8; ++q) bsplit(v[q], h[q], l[q]);
            *(uint4*)&AH[srow * 24 + sh * 8] =
                make_uint4(pack_bf2(h[0],h[1]), pack_bf2(h[2],h[3]),
                           pack_bf2(h[4],h[5]), pack_bf2(h[6],h[7]));
            *(uint4*)&AL[srow * 24 + sh * 8] =
                make_uint4(pack_bf2(l[0],l[1]), pack_bf2(l[2],l[3]),
                           pack_bf2(l[4],l[5]), pack_bf2(l[6],l[7]));
        }
        if (tid < 128) {
            *(uint4*)&BHs[srow * 24 + sh * 8] =
                *(const uint4*)&Bh[(size_t)srow * 128 + k0 + sh * 8];
            *(uint4*)&BLs[srow * 24 + sh * 8] =
                *(const uint4*)&Bl[(size_t)srow * 128 + k0 + sh * 8];
        }
        __syncthreads();

        uint32_t ah[4], al[4];
        int arow = wid * 16 + a_r0;
        LDSM_X4(ah[0], ah[1], ah[2], ah[3], uAH + arow * 48 + a_ch * 16);
        LDSM_X4(al[0], al[1], al[2], al[3], uAL + arow * 48 + a_ch * 16);
#pragma unroll
        for (int np = 0; np < 4; ++np) {
            int bn = np * 16 + b_n0;
            uint32_t bh[4], bl[4];
            LDSM_X4(bh[0], bh[1], bh[2], bh[3], uBH + bn * 48 + b_ch * 16);
            LDSM_X4(bl[0], bl[1], bl[2], bl[3], uBL + bn * 48 + b_ch * 16);
#pragma unroll
            for (int t = 0; t < 2; ++t) {
                float* a4 = acc[np * 2 + t];
                MMA_BF16(a4, ah, bh[2 * t], bh[2 * t + 1]);
                MMA_BF16(a4, ah, bl[2 * t], bl[2 * t + 1]);
                MMA_BF16(a4, al, bh[2 * t], bh[2 * t + 1]);
            }
        }
        __syncthreads();
    }

    const int lr = lane >> 2;
    const int lc = (lane & 3) * 2;
#pragma unroll
    for (int g = 0; g < 8; ++g) {
        int col = g * 8 + lc;
        if (col >= 40) continue;
        float2 bv = *(const float2*)&bias[col];
#pragma unroll
        for (int half = 0; half < 2; ++half) {
            int r = bm + wid * 16 + lr + half * 8;
            if (r >= M) continue;
            float z0 = acc[g][2 * half + 0] + bv.x;
            float z1 = acc[g][2 * half + 1] + bv.y;
            *(float2*)&out[(size_t)r * 40 + col] = make_float2(z0, z1);
        }
    }
}

// ---------------------------------------------------------------------------
extern "C" void kernel_launch(void* const* d_in, const int* in_sizes, int n_in,
                              void* d_out, int out_size) {
    const float* x   = (const float*)d_in[0];
    const int*   ei  = (const int*)  d_in[1];
    const float* emb = (const float*)d_in[2];
    const float* wx1 = (const float*)d_in[3];
    const float* bx1 = (const float*)d_in[4];
    const float* wx2 = (const float*)d_in[5];
    const float* bx2 = (const float*)d_in[6];
    const float* wa1 = (const float*)d_in[7];
    const float* ba1 = (const float*)d_in[8];
    const float* wa2 = (const float*)d_in[9];
    const float* ba2 = (const float*)d_in[10];
    const float* ww1 = (const float*)d_in[11];
    const float* bw1 = (const float*)d_in[12];
    const float* wc  = (const float*)d_in[13];
    const float* bc  = (const float*)d_in[14];
    float* out = (float*)d_out;

    const int M = in_sizes[0] / INDIM;   // 100000
    const int E = in_sizes[1] / 2;       // 1600000

    float *hx, *ha, *z5a, *z5b, *uv, *b5, *zero;
    __nv_bfloat16 *wt, *xs, *hb, *h2b, *aggb;
    int *cnt, *cur, *off, *bins;
    cudaGetSymbolAddress((void**)&hx,   g_hx);
    cudaGetSymbolAddress((void**)&ha,   g_ha);
    cudaGetSymbolAddress((void**)&z5a,  g_z5a);
    cudaGetSymbolAddress((void**)&z5b,  g_z5b);
    cudaGetSymbolAddress((void**)&uv,   g_uv);
    cudaGetSymbolAddress((void**)&b5,   g_b5);
    cudaGetSymbolAddress((void**)&zero, g_zero);
    cudaGetSymbolAddress((void**)&wt,   g_wt);
    cudaGetSymbolAddress((void**)&xs,   g_xs);
    cudaGetSymbolAddress((void**)&hb,   g_hb);
    cudaGetSymbolAddress((void**)&h2b,  g_h2b);
    cudaGetSymbolAddress((void**)&aggb, g_aggb);
    cudaGetSymbolAddress((void**)&cnt,  g_cnt);
    cudaGetSymbolAddress((void**)&cur,  g_cur);
    cudaGetSymbolAddress((void**)&off,  g_off);
    cudaGetSymbolAddress((void**)&bins, g_bins);

    __nv_bfloat16 *xsh = xs,   *xsl = xs   + (size_t)M * INDIM;
    __nv_bfloat16 *hbh = hb,   *hbl = hb   + (size_t)M * HID;
    __nv_bfloat16 *h2h = h2b,  *h2l = h2b  + (size_t)M * HID;
    __nv_bfloat16 *agh = aggb, *agl = aggb + (size_t)M * HID;
    __nv_bfloat16 *W1h  = wt,           *W1l  = wt + 32768;
    __nv_bfloat16 *WB2h = wt + 65536,   *WB2l = wt + 98304;
    __nv_bfloat16 *W3h  = wt + 131072,  *W3l  = wt + 147456;
    __nv_bfloat16 *WB4h = wt + 163840,  *WB4l = wt + 196608;
    __nv_bfloat16 *W6h  = wt + 229376,  *W6l  = wt + 237568;

    static cudaStream_t s_side = nullptr;
    static cudaEvent_t  ev_fork = nullptr, ev_prep = nullptr, ev_join = nullptr;
    if (s_side == nullptr) {
        cudaStreamCreateWithFlags(&s_side, cudaStreamNonBlocking);
        cudaEventCreateWithFlags(&ev_fork, cudaEventDisableTiming);
        cudaEventCreateWithFlags(&ev_prep, cudaEventDisableTiming);
        cudaEventCreateWithFlags(&ev_join, cudaEventDisableTiming);
        const int SM = 81920;
        cudaFuncSetAttribute(mma_split<INDIM>,
                             cudaFuncAttributeMaxDynamicSharedMemorySize, SM);
        cudaFuncSetAttribute(mma_split<HID>,
                             cudaFuncAttributeMaxDynamicSharedMemorySize, SM);
        cudaFuncSetAttribute(mma_fused2,
                             cudaFuncAttributeMaxDynamicSharedMemorySize, SM);
    }

    const int gb  = (M + 127) / 128;   // 782
    const int SMB = 81920;

    // ---- fork ----
    cudaEventRecord(ev_fork, 0);
    cudaStreamWaitEvent(s_side, ev_fork, 0);

    // side: binning + gather -> aggb planes
    zero_cnt<<<(M + 255) / 256, 256, 0, s_side>>>(cnt, cur, M);
    count_kernel<<<1184, 256, 0, s_side>>>(ei, cnt, E);
    scan_kernel<<<1, 1024, 0, s_side>>>(cnt, off, M);
    fill_kernel<<<1184, 256, 0, s_side>>>(ei, off, cur, bins, E);
    gather_kernel<<<(M * 32 + 255) / 256, 256, 0, s_side>>>(off, bins, emb, agh, agl, M);

    // main: composites + preps
    compose_kernel<<<dim3(128, 2), 128>>>(wx2, wa2, ww1, uv);
    bias5_kernel<<<1, 128>>>(bx2, ba2, bw1, ww1, b5);
    prep_all3<<<(122880 + 255) / 256, 256>>>(wx1, wx2, wa1, wa2, uv, wc, wt);
    const int n4x = M * (INDIM / 4);
    prep_x<<<(n4x + 255) / 256, 256>>>((const float4*)x, xsh, xsl, n4x);
    cudaEventRecord(ev_prep, 0);

    // side continues: G3 then fused [G4|G5b]
    cudaStreamWaitEvent(s_side, ev_prep, 0);
    // G3: h2b = relu(aggb @ wa1 + ba1)
    mma_split<HID><<<gb, 256, SMB, s_side>>>(agh, agl, W3h, W3l, ba1, h2h, h2l, M);
    // [G4|G5b]: y0 ha = h2b@wa2 + ba2; y1 z5b = h2b@V
    mma_fused2<<<dim3(gb, 2), 256, SMB, s_side>>>(h2h, h2l, WB4h, WB4l,
                                                  ba2, ha, zero, z5b, M);
    cudaEventRecord(ev_join, s_side);

    // main: G1 then fused [G2|G5a]
    // G1: hb = relu(xs @ wx1 + bx1)
    mma_split<INDIM><<<gb, 256, SMB>>>(xsh, xsl, W1h, W1l, bx1, hbh, hbl, M);
    // [G2|G5a]: y0 hx = hb@wx2 + bx2; y1 z5a = hb@U + b5'
    mma_fused2<<<dim3(gb, 2), 256, SMB>>>(hbh, hbl, WB2h, WB2l,
                                          bx2, hx, b5, z5a, M);

    // ---- join ----
    cudaStreamWaitEvent(0, ev_join, 0);

    // G6: combine + classifier
    mma_out4<<<gb, 256>>>(z5a, z5b, hx, ha, W6h, W6l, bc, out, M);
}